// round 13
// baseline (speedup 1.0000x reference)
#include <cuda_runtime.h>
#include <cuda_fp16.h>
#include <math.h>
#include <stdint.h>

// Problem constants
#define BB 4
#define SS 2048
#define DD 1024
#define HH 16
#define DKK 64
#define MTOT (BB * SS)   // 8192

// Scratch device globals
__device__ __half g_Q[BB * HH * SS * DKK];    // [B,H,S,DK]
__device__ __half g_K[BB * HH * SS * DKK];
__device__ __half g_V[BB * HH * SS * DKK];
__device__ __half g_ATT[(size_t)MTOT * DD];   // [B,S,D]
__device__ __half g_qh[(size_t)MTOT * DD];
__device__ __half g_kh[(size_t)MTOT * DD];
__device__ __half g_vh[(size_t)MTOT * DD];
__device__ __half g_wqh[DD * DD];
__device__ __half g_wkh[DD * DD];
__device__ __half g_wvh[DD * DD];
__device__ __half g_woh[DD * DD];

// ---------------------------------------------------------------------------
// Helpers
// ---------------------------------------------------------------------------
__device__ __forceinline__ uint32_t su(const void* p) {
    return (uint32_t)__cvta_generic_to_shared(p);
}
__device__ __forceinline__ void ldm4(uint32_t* r, uint32_t a) {
    asm volatile("ldmatrix.sync.aligned.m8n8.x4.shared.b16 {%0,%1,%2,%3},[%4];"
        : "=r"(r[0]), "=r"(r[1]), "=r"(r[2]), "=r"(r[3]) : "r"(a));
}
__device__ __forceinline__ void ldm4t(uint32_t* r, uint32_t a) {
    asm volatile("ldmatrix.sync.aligned.m8n8.x4.trans.shared.b16 {%0,%1,%2,%3},[%4];"
        : "=r"(r[0]), "=r"(r[1]), "=r"(r[2]), "=r"(r[3]) : "r"(a));
}
__device__ __forceinline__ void mma16(float* d, const uint32_t* a, const uint32_t* b) {
    asm volatile(
        "mma.sync.aligned.m16n8k16.row.col.f32.f16.f16.f32 "
        "{%0,%1,%2,%3},{%4,%5,%6,%7},{%8,%9},{%0,%1,%2,%3};"
        : "+f"(d[0]), "+f"(d[1]), "+f"(d[2]), "+f"(d[3])
        : "r"(a[0]), "r"(a[1]), "r"(a[2]), "r"(a[3]), "r"(b[0]), "r"(b[1]));
}
__device__ __forceinline__ uint32_t packh2(float x, float y) {
    __half2 h = __floats2half2_rn(x, y);
    return *(uint32_t*)&h;
}
__device__ __forceinline__ void cpa16(uint32_t d, const void* s) {
    asm volatile("cp.async.cg.shared.global [%0],[%1],16;" :: "r"(d), "l"(s));
}
#define CP_COMMIT() asm volatile("cp.async.commit_group;")

// ---------------------------------------------------------------------------
// Merged f32 -> f16 convert for all 7 arrays (one launch)
// ---------------------------------------------------------------------------
#define NACT4 (MTOT * DD / 4)
#define NW4   (DD * DD / 4)
#define NCONV_TOT (3 * NACT4 + 4 * NW4)

__global__ __launch_bounds__(256) void f2h_all_kernel(
    const float4* __restrict__ q, const float4* __restrict__ k,
    const float4* __restrict__ v,
    const float4* __restrict__ wq, const float4* __restrict__ wk,
    const float4* __restrict__ wv, const float4* __restrict__ wo)
{
    int i = blockIdx.x * 256 + threadIdx.x;
    if (i >= NCONV_TOT) return;
    const float4* src;
    uint2* dst;
    int off;
    if (i < 3 * NACT4) {
        int w = i / NACT4;
        off = i - w * NACT4;
        src = (w == 0) ? q : (w == 1) ? k : v;
        dst = (uint2*)((w == 0) ? g_qh : (w == 1) ? g_kh : g_vh);
    } else {
        int j = i - 3 * NACT4;
        int w = j / NW4;
        off = j - w * NW4;
        src = (w == 0) ? wq : (w == 1) ? wk : (w == 2) ? wv : wo;
        dst = (uint2*)((w == 0) ? g_wqh : (w == 1) ? g_wkh : (w == 2) ? g_wvh : g_woh);
    }
    float4 val = src[off];
    dst[off] = make_uint2(packh2(val.x, val.y), packh2(val.z, val.w));
}

// ---------------------------------------------------------------------------
// Pipelined FP16 GEMM core: C = A @ W^T, tile 128x64, K=1024, k-chunk 64.
// 2-stage ring with compute-overlapped prefetch. 8 warps 4(m)x2(n),
// warp tile 32x32. Rows padded to 72 halves (144B).
// ---------------------------------------------------------------------------
#define PR 72
#define A_STG (128 * PR * 2)            // 18432 B
#define W_STG (64 * PR * 2)             //  9216 B
#define GEMM_SMEM (2 * (A_STG + W_STG)) // 55296 B

__device__ __forceinline__ void gemm_pipe_core(
    const __half* __restrict__ A, const __half* __restrict__ W,
    __half* smem, float acc[2][4][4])
{
    const int t    = threadIdx.x;
    const int lane = t & 31;
    const int warp = t >> 5;
    const int wm   = warp >> 1;    // 0..3
    const int wn   = warp & 1;     // 0..1

    const int m0 = blockIdx.x * 128;
    const int n0 = blockIdx.y * 64;

    const uint32_t asB = su(smem);
    const uint32_t wsB = asB + 2 * A_STG;

    const int r0 = t >> 3;          // 0..31
    const int c  = t & 7;
    const __half* aS = A + (size_t)(m0 + r0) * DD + c * 8;
    const __half* wS = W + (size_t)(n0 + r0) * DD + c * 8;
    const uint32_t cb = (uint32_t)(r0 * (PR * 2) + c * 16);

    const int rowoff = (lane & 7) + ((lane >> 3) & 1) * 8;
    const int akoff  = ((lane >> 4) & 1) * 8;
    const int noff   = (lane & 7) + ((lane >> 4) & 1) * 8;
    const int bkoff  = ((lane >> 3) & 1) * 8;
    uint32_t aAddr[2], bAddr[2];
#pragma unroll
    for (int mi = 0; mi < 2; mi++)
        aAddr[mi] = asB + ((wm * 32 + mi * 16 + rowoff) * PR + akoff) * 2;
#pragma unroll
    for (int p = 0; p < 2; p++)
        bAddr[p] = wsB + ((wn * 32 + p * 16 + noff) * PR + bkoff) * 2;

    auto issue = [&](int s) {
        const int ko = s * 64;
        const uint32_t st = (uint32_t)(s & 1);
#pragma unroll
        for (int i = 0; i < 4; i++)
            cpa16(asB + st * A_STG + cb + (uint32_t)(32 * i) * (PR * 2),
                  aS + (size_t)(32 * i) * DD + ko);
#pragma unroll
        for (int i = 0; i < 2; i++)
            cpa16(wsB + st * W_STG + cb + (uint32_t)(32 * i) * (PR * 2),
                  wS + (size_t)(32 * i) * DD + ko);
        CP_COMMIT();
    };

    issue(0);

    const int NIT = DD / 64;   // 16
    for (int it = 0; it < NIT; it++) {
        asm volatile("cp.async.wait_group 0;");
        __syncthreads();
        if (it + 1 < NIT) issue(it + 1);

        const uint32_t offA = (uint32_t)(it & 1) * A_STG;
        const uint32_t offB = (uint32_t)(it & 1) * W_STG;
#pragma unroll
        for (int ks = 0; ks < 4; ks++) {
            uint32_t af[2][4];
#pragma unroll
            for (int mi = 0; mi < 2; mi++)
                ldm4(af[mi], aAddr[mi] + offA + ks * 32);
            uint32_t bf[4][2];
#pragma unroll
            for (int p = 0; p < 2; p++) {
                uint32_t tmp[4];
                ldm4(tmp, bAddr[p] + offB + ks * 32);
                bf[2 * p][0] = tmp[0]; bf[2 * p][1] = tmp[1];
                bf[2 * p + 1][0] = tmp[2]; bf[2 * p + 1][1] = tmp[3];
            }
#pragma unroll
            for (int mi = 0; mi < 2; mi++)
#pragma unroll
                for (int ni = 0; ni < 4; ni++)
                    mma16(acc[mi][ni], af[mi], bf[ni]);
        }
    }
}

// ---------------------------------------------------------------------------
// QKV projections (half in/out): Y = X @ W^T + b -> head-split [B,H,S,DK]
// ---------------------------------------------------------------------------
__global__ __launch_bounds__(256, 3) void qkv_proj_kernel(
    const float* __restrict__ bq, const float* __restrict__ bk,
    const float* __restrict__ bv)
{
    extern __shared__ __half smem[];

    const __half* A; const __half* W; const float* bias; __half* out;
    if (blockIdx.z == 0)      { A = g_qh; W = g_wqh; bias = bq; out = g_Q; }
    else if (blockIdx.z == 1) { A = g_kh; W = g_wkh; bias = bk; out = g_K; }
    else                      { A = g_vh; W = g_wvh; bias = bv; out = g_V; }

    float acc[2][4][4];
#pragma unroll
    for (int a = 0; a < 2; a++)
#pragma unroll
        for (int b = 0; b < 4; b++)
#pragma unroll
            for (int c = 0; c < 4; c++) acc[a][b][c] = 0.f;

    gemm_pipe_core(A, W, smem, acc);

    const int lane = threadIdx.x & 31;
    const int warp = threadIdx.x >> 5;
    const int wm = warp >> 1, wn = warp & 1;
    const int qq = lane & 3, l4 = lane >> 2;
    const int m0 = blockIdx.x * 128;
    const int n0 = blockIdx.y * 64;

#pragma unroll
    for (int mi = 0; mi < 2; mi++) {
#pragma unroll
        for (int rr = 0; rr < 2; rr++) {
            int m = m0 + wm * 32 + mi * 16 + l4 + rr * 8;
            int b = m >> 11;
            int s = m & 2047;
#pragma unroll
            for (int ni = 0; ni < 4; ni++) {
                int n  = n0 + wn * 32 + ni * 8 + 2 * qq;
                int h  = n >> 6;
                int dk = n & 63;
                __half2 hv = __floats2half2_rn(acc[mi][ni][rr * 2 + 0] + bias[n],
                                               acc[mi][ni][rr * 2 + 1] + bias[n + 1]);
                *(__half2*)&out[((size_t)(b * HH + h) * SS + s) * DKK + dk] = hv;
            }
        }
    }
}

// ---------------------------------------------------------------------------
// Output projection: out(f32) = g_ATT(half) @ Wo^T + bo
// ---------------------------------------------------------------------------
__global__ __launch_bounds__(256, 3) void out_proj_kernel(
    const float* __restrict__ bo, float* __restrict__ out)
{
    extern __shared__ __half smem[];

    float acc[2][4][4];
#pragma unroll
    for (int a = 0; a < 2; a++)
#pragma unroll
        for (int b = 0; b < 4; b++)
#pragma unroll
            for (int c = 0; c < 4; c++) acc[a][b][c] = 0.f;

    gemm_pipe_core(g_ATT, g_woh, smem, acc);

    const int lane = threadIdx.x & 31;
    const int warp = threadIdx.x >> 5;
    const int wm = warp >> 1, wn = warp & 1;
    const int qq = lane & 3, l4 = lane >> 2;
    const int m0 = blockIdx.x * 128;
    const int n0 = blockIdx.y * 64;

#pragma unroll
    for (int mi = 0; mi < 2; mi++) {
#pragma unroll
        for (int rr = 0; rr < 2; rr++) {
            int m = m0 + wm * 32 + mi * 16 + l4 + rr * 8;
#pragma unroll
            for (int ni = 0; ni < 4; ni++) {
                int n = n0 + wn * 32 + ni * 8 + 2 * qq;
                float2 rv;
                rv.x = acc[mi][ni][rr * 2 + 0] + bo[n];
                rv.y = acc[mi][ni][rr * 2 + 1] + bo[n + 1];
                *(float2*)&out[(size_t)m * DD + n] = rv;
            }
        }
    }
}

// ---------------------------------------------------------------------------
// Flash attention (causal), FP16 mma + ldmatrix + cp.async.
// 4-stage KV ring, tiles processed in PAIRS: one wait+sync per 128 keys.
// Heavy q-tiles launch first (bx reversed) for better tail packing.
// ---------------------------------------------------------------------------
#define AR 72
#define Q_HALVES (128 * AR)
#define KV_HALVES (64 * AR)
#define ATTN_SMEM ((Q_HALVES + 8 * KV_HALVES) * 2)   // 92160 B

__global__ __launch_bounds__(256, 2) void attn_kernel()
{
    extern __shared__ __half sm[];
    __half* Qs = sm;

    const int t    = threadIdx.x;
    const int lane = t & 31;
    const int w    = t >> 5;
    const int qq   = lane & 3;
    const int l4   = lane >> 2;

    const int bx = (int)gridDim.x - 1 - (int)blockIdx.x;   // heavy first
    const int h  = blockIdx.y;
    const int b  = blockIdx.z;

    const __half* Qbase = g_Q + ((size_t)(b * HH + h) * SS) * DKK;
    const __half* Kbase = g_K + ((size_t)(b * HH + h) * SS) * DKK;
    const __half* Vbase = g_V + ((size_t)(b * HH + h) * SS) * DKK;

    uint32_t ksB[4], vsB[4];
#pragma unroll
    for (int i = 0; i < 4; i++) {
        ksB[i] = su(Qs + Q_HALVES + (size_t)i * KV_HALVES);
        vsB[i] = su(Qs + Q_HALVES + (size_t)(4 + i) * KV_HALVES);
    }

    const int qr = t >> 3;
    const int qc = (t & 7) * 16;
    const int kr = t >> 3;
    const int kc = (t & 7) * 16;

    // Issue Q (own commit group)
    {
        uint32_t qdst = su(Qs);
#pragma unroll
        for (int i = 0; i < 4; i++) {
            int r = qr + 32 * i;
            cpa16(qdst + r * (AR * 2) + qc, (const char*)(Qbase + (size_t)(bx * 128 + r) * DKK) + qc);
        }
    }
    CP_COMMIT();

    // Issue a PAIR of KV tiles as one commit group
    auto issue_group = [&](int g) {
#pragma unroll
        for (int tt = 0; tt < 2; tt++) {
            const int kt = 2 * g + tt;
            const __half* Kt = Kbase + (size_t)kt * 64 * DKK;
            const __half* Vt = Vbase + (size_t)kt * 64 * DKK;
            const int st = kt & 3;
#pragma unroll
            for (int i = 0; i < 2; i++) {
                int r = kr + 32 * i;
                cpa16(ksB[st] + r * (AR * 2) + kc, (const char*)(Kt + (size_t)r * DKK) + kc);
                cpa16(vsB[st] + r * (AR * 2) + kc, (const char*)(Vt + (size_t)r * DKK) + kc);
            }
        }
        CP_COMMIT();
    };

    issue_group(0);

    // Wait for Q (group 0 may remain in flight), extract Q fragments
    asm volatile("cp.async.wait_group 1;");
    __syncthreads();

    const int rowoff = (lane & 7) + ((lane >> 3) & 1) * 8;
    const int akoff  = ((lane >> 4) & 1) * 8;
    const int noff   = (lane & 7) + ((lane >> 4) & 1) * 8;
    const int bkoff  = ((lane >> 3) & 1) * 8;
    const int vkoff  = ((lane >> 4) & 1) * 8;

    uint32_t aq[4][4];
#pragma unroll
    for (int g = 0; g < 4; g++)
        ldm4(aq[g], su(&Qs[(16 * w + rowoff) * AR + g * 16 + akoff]));

    const int rl = 16 * w + l4;
    const int row_lo = bx * 128 + rl;
    const int row_hi = row_lo + 8;

    float m_lo = -1e30f, m_hi = -1e30f, l_lo = 0.f, l_hi = 0.f;
    float Oacc[8][4];
#pragma unroll
    for (int j = 0; j < 8; j++)
#pragma unroll
        for (int c = 0; c < 4; c++) Oacc[j][c] = 0.f;

    // Process one 64-key tile (stage kt&3)
    auto process_tile = [&](int kt) {
        const int st = kt & 3;

        float Sacc[8][4];
#pragma unroll
        for (int j = 0; j < 8; j++)
#pragma unroll
            for (int c = 0; c < 4; c++) Sacc[j][c] = 0.f;

#pragma unroll
        for (int g = 0; g < 4; g++) {
#pragma unroll
            for (int p = 0; p < 4; p++) {
                uint32_t tmp[4];
                ldm4(tmp, ksB[st] + ((p * 16 + noff) * AR + g * 16 + bkoff) * 2);
                mma16(Sacc[2 * p],     aq[g], tmp);
                mma16(Sacc[2 * p + 1], aq[g], tmp + 2);
            }
        }

#pragma unroll
        for (int j = 0; j < 8; j++)
#pragma unroll
            for (int c = 0; c < 4; c++) Sacc[j][c] *= 0.125f;

        if (kt >= 2 * bx) {
#pragma unroll
            for (int j = 0; j < 8; j++) {
                int col = kt * 64 + 8 * j + 2 * qq;
                if (col     > row_lo) Sacc[j][0] = -1e30f;
                if (col + 1 > row_lo) Sacc[j][1] = -1e30f;
                if (col     > row_hi) Sacc[j][2] = -1e30f;
                if (col + 1 > row_hi) Sacc[j][3] = -1e30f;
            }
        }

        float mt_lo = -1e30f, mt_hi = -1e30f;
#pragma unroll
        for (int j = 0; j < 8; j++) {
            mt_lo = fmaxf(mt_lo, fmaxf(Sacc[j][0], Sacc[j][1]));
            mt_hi = fmaxf(mt_hi, fmaxf(Sacc[j][2], Sacc[j][3]));
        }
        mt_lo = fmaxf(mt_lo, __shfl_xor_sync(0xffffffffu, mt_lo, 1));
        mt_lo = fmaxf(mt_lo, __shfl_xor_sync(0xffffffffu, mt_lo, 2));
        mt_hi = fmaxf(mt_hi, __shfl_xor_sync(0xffffffffu, mt_hi, 1));
        mt_hi = fmaxf(mt_hi, __shfl_xor_sync(0xffffffffu, mt_hi, 2));

        float mn_lo = fmaxf(m_lo, mt_lo);
        float mn_hi = fmaxf(m_hi, mt_hi);
        float al_lo = __expf(m_lo - mn_lo);
        float al_hi = __expf(m_hi - mn_hi);

        float ls_lo = 0.f, ls_hi = 0.f;
#pragma unroll
        for (int j = 0; j < 8; j++) {
            Sacc[j][0] = __expf(Sacc[j][0] - mn_lo);
            Sacc[j][1] = __expf(Sacc[j][1] - mn_lo);
            Sacc[j][2] = __expf(Sacc[j][2] - mn_hi);
            Sacc[j][3] = __expf(Sacc[j][3] - mn_hi);
            ls_lo += Sacc[j][0] + Sacc[j][1];
            ls_hi += Sacc[j][2] + Sacc[j][3];
        }
        ls_lo += __shfl_xor_sync(0xffffffffu, ls_lo, 1);
        ls_lo += __shfl_xor_sync(0xffffffffu, ls_lo, 2);
        ls_hi += __shfl_xor_sync(0xffffffffu, ls_hi, 1);
        ls_hi += __shfl_xor_sync(0xffffffffu, ls_hi, 2);

        l_lo = l_lo * al_lo + ls_lo;
        l_hi = l_hi * al_hi + ls_hi;
        m_lo = mn_lo;
        m_hi = mn_hi;

        uint32_t ap[4][4];
#pragma unroll
        for (int g = 0; g < 4; g++) {
            ap[g][0] = packh2(Sacc[2 * g][0],     Sacc[2 * g][1]);
            ap[g][1] = packh2(Sacc[2 * g][2],     Sacc[2 * g][3]);
            ap[g][2] = packh2(Sacc[2 * g + 1][0], Sacc[2 * g + 1][1]);
            ap[g][3] = packh2(Sacc[2 * g + 1][2], Sacc[2 * g + 1][3]);
        }

#pragma unroll
        for (int j = 0; j < 8; j++) {
            Oacc[j][0] *= al_lo;
            Oacc[j][1] *= al_lo;
            Oacc[j][2] *= al_hi;
            Oacc[j][3] *= al_hi;
        }

#pragma unroll
        for (int g = 0; g < 4; g++) {
#pragma unroll
            for (int p = 0; p < 4; p++) {
                uint32_t tmp[4];
                ldm4t(tmp, vsB[st] + ((g * 16 + rowoff) * AR + p * 16 + vkoff) * 2);
                mma16(Oacc[2 * p],     ap[g], tmp);
                mma16(Oacc[2 * p + 1], ap[g], tmp + 2);
            }
        }
    };

    // Main loop: bx+1 iterations, each consumes a pair of tiles.
    // Iter j: wait group j (all outstanding), sync (all warps done with group
    // j-1, whose stages group j+1 reuses), prefetch group j+1, compute pair.
    for (int j = 0; j <= bx; j++) {
        asm volatile("cp.async.wait_group 0;");
        __syncthreads();
        if (j < bx) issue_group(j + 1);
        process_tile(2 * j);
        process_tile(2 * j + 1);
    }

    float il_lo = 1.f / l_lo;
    float il_hi = 1.f / l_hi;
    __half* out_lo = g_ATT + ((size_t)(b * SS + row_lo)) * DD + h * DKK;
    __half* out_hi = g_ATT + ((size_t)(b * SS + row_hi)) * DD + h * DKK;
#pragma unroll
    for (int j = 0; j < 8; j++) {
        int dk = 8 * j + 2 * qq;
        *(__half2*)&out_lo[dk] = __floats2half2_rn(Oacc[j][0] * il_lo, Oacc[j][1] * il_lo);
        *(__half2*)&out_hi[dk] = __floats2half2_rn(Oacc[j][2] * il_hi, Oacc[j][3] * il_hi);
    }
}

// ---------------------------------------------------------------------------
// Entry point. Inputs: q,k,v,mask,w_q,b_q,w_k,b_k,w_v,b_v,w_o,b_o
// ---------------------------------------------------------------------------
extern "C" void kernel_launch(void* const* d_in, const int* in_sizes, int n_in,
                              void* d_out, int out_size)
{
    const float* q  = (const float*)d_in[0];
    const float* k  = (const float*)d_in[1];
    const float* v  = (const float*)d_in[2];
    const float* wq = (const float*)d_in[4];
    const float* bq = (const float*)d_in[5];
    const float* wk = (const float*)d_in[6];
    const float* bk = (const float*)d_in[7];
    const float* wv = (const float*)d_in[8];
    const float* bv = (const float*)d_in[9];
    const float* wo = (const float*)d_in[10];
    const float* bo = (const float*)d_in[11];
    float* out = (float*)d_out;

    f2h_all_kernel<<<(NCONV_TOT + 255) / 256, 256>>>(
        (const float4*)q, (const float4*)k, (const float4*)v,
        (const float4*)wq, (const float4*)wk, (const float4*)wv, (const float4*)wo);

    cudaFuncSetAttribute(qkv_proj_kernel, cudaFuncAttributeMaxDynamicSharedMemorySize, GEMM_SMEM);
    dim3 gproj(MTOT / 128, DD / 64, 3);
    qkv_proj_kernel<<<gproj, 256, GEMM_SMEM>>>(bq, bk, bv);

    cudaFuncSetAttribute(attn_kernel, cudaFuncAttributeMaxDynamicSharedMemorySize, ATTN_SMEM);
    dim3 gattn(SS / 128, HH, BB);
    attn_kernel<<<gattn, 256, ATTN_SMEM>>>();

    cudaFuncSetAttribute(out_proj_kernel, cudaFuncAttributeMaxDynamicSharedMemorySize, GEMM_SMEM);
    dim3 gout(MTOT / 128, DD / 64, 1);
    out_proj_kernel<<<gout, 256, GEMM_SMEM>>>(bo, out);
}

// round 14
// speedup vs baseline: 1.0045x; 1.0045x over previous
#include <cuda_runtime.h>
#include <cuda_fp16.h>
#include <math.h>
#include <stdint.h>

// Problem constants
#define BB 4
#define SS 2048
#define DD 1024
#define HH 16
#define DKK 64
#define MTOT (BB * SS)   // 8192

// Scratch device globals
__device__ __half g_Q[BB * HH * SS * DKK];    // [B,H,S,DK]
__device__ __half g_K[BB * HH * SS * DKK];
__device__ __half g_V[BB * HH * SS * DKK];
__device__ __half g_ATT[(size_t)MTOT * DD];   // [B,S,D]
__device__ __half g_qh[(size_t)MTOT * DD];
__device__ __half g_kh[(size_t)MTOT * DD];
__device__ __half g_vh[(size_t)MTOT * DD];
__device__ __half g_wqh[DD * DD];
__device__ __half g_wkh[DD * DD];
__device__ __half g_wvh[DD * DD];
__device__ __half g_woh[DD * DD];

// ---------------------------------------------------------------------------
// Helpers
// ---------------------------------------------------------------------------
__device__ __forceinline__ uint32_t su(const void* p) {
    return (uint32_t)__cvta_generic_to_shared(p);
}
__device__ __forceinline__ void ldm4(uint32_t* r, uint32_t a) {
    asm volatile("ldmatrix.sync.aligned.m8n8.x4.shared.b16 {%0,%1,%2,%3},[%4];"
        : "=r"(r[0]), "=r"(r[1]), "=r"(r[2]), "=r"(r[3]) : "r"(a));
}
__device__ __forceinline__ void ldm4t(uint32_t* r, uint32_t a) {
    asm volatile("ldmatrix.sync.aligned.m8n8.x4.trans.shared.b16 {%0,%1,%2,%3},[%4];"
        : "=r"(r[0]), "=r"(r[1]), "=r"(r[2]), "=r"(r[3]) : "r"(a));
}
__device__ __forceinline__ void mma16(float* d, const uint32_t* a, const uint32_t* b) {
    asm volatile(
        "mma.sync.aligned.m16n8k16.row.col.f32.f16.f16.f32 "
        "{%0,%1,%2,%3},{%4,%5,%6,%7},{%8,%9},{%0,%1,%2,%3};"
        : "+f"(d[0]), "+f"(d[1]), "+f"(d[2]), "+f"(d[3])
        : "r"(a[0]), "r"(a[1]), "r"(a[2]), "r"(a[3]), "r"(b[0]), "r"(b[1]));
}
__device__ __forceinline__ uint32_t packh2(float x, float y) {
    __half2 h = __floats2half2_rn(x, y);
    return *(uint32_t*)&h;
}
__device__ __forceinline__ void cpa16(uint32_t d, const void* s) {
    asm volatile("cp.async.cg.shared.global [%0],[%1],16;" :: "r"(d), "l"(s));
}
#define CP_COMMIT() asm volatile("cp.async.commit_group;")

// ---------------------------------------------------------------------------
// Merged f32 -> f16 convert for all 7 arrays (one launch)
// ---------------------------------------------------------------------------
#define NACT4 (MTOT * DD / 4)
#define NW4   (DD * DD / 4)
#define NCONV_TOT (3 * NACT4 + 4 * NW4)

__global__ __launch_bounds__(256) void f2h_all_kernel(
    const float4* __restrict__ q, const float4* __restrict__ k,
    const float4* __restrict__ v,
    const float4* __restrict__ wq, const float4* __restrict__ wk,
    const float4* __restrict__ wv, const float4* __restrict__ wo)
{
    int i = blockIdx.x * 256 + threadIdx.x;
    if (i >= NCONV_TOT) return;
    const float4* src;
    uint2* dst;
    int off;
    if (i < 3 * NACT4) {
        int w = i / NACT4;
        off = i - w * NACT4;
        src = (w == 0) ? q : (w == 1) ? k : v;
        dst = (uint2*)((w == 0) ? g_qh : (w == 1) ? g_kh : g_vh);
    } else {
        int j = i - 3 * NACT4;
        int w = j / NW4;
        off = j - w * NW4;
        src = (w == 0) ? wq : (w == 1) ? wk : (w == 2) ? wv : wo;
        dst = (uint2*)((w == 0) ? g_wqh : (w == 1) ? g_wkh : (w == 2) ? g_wvh : g_woh);
    }
    float4 val = src[off];
    dst[off] = make_uint2(packh2(val.x, val.y), packh2(val.z, val.w));
}

// ---------------------------------------------------------------------------
// Pipelined FP16 GEMM core: C = A @ W^T, tile 128x64, K=1024, k-chunk 64.
// 2-stage ring with compute-overlapped prefetch. 8 warps 4(m)x2(n),
// warp tile 32x32. Rows padded to 72 halves (144B).
// ---------------------------------------------------------------------------
#define PR 72
#define A_STG (128 * PR * 2)            // 18432 B
#define W_STG (64 * PR * 2)             //  9216 B
#define GEMM_SMEM (2 * (A_STG + W_STG)) // 55296 B

__device__ __forceinline__ void gemm_pipe_core(
    const __half* __restrict__ A, const __half* __restrict__ W,
    __half* smem, float acc[2][4][4])
{
    const int t    = threadIdx.x;
    const int lane = t & 31;
    const int warp = t >> 5;
    const int wm   = warp >> 1;    // 0..3
    const int wn   = warp & 1;     // 0..1

    const int m0 = blockIdx.x * 128;
    const int n0 = blockIdx.y * 64;

    const uint32_t asB = su(smem);
    const uint32_t wsB = asB + 2 * A_STG;

    const int r0 = t >> 3;          // 0..31
    const int c  = t & 7;
    const __half* aS = A + (size_t)(m0 + r0) * DD + c * 8;
    const __half* wS = W + (size_t)(n0 + r0) * DD + c * 8;
    const uint32_t cb = (uint32_t)(r0 * (PR * 2) + c * 16);

    const int rowoff = (lane & 7) + ((lane >> 3) & 1) * 8;
    const int akoff  = ((lane >> 4) & 1) * 8;
    const int noff   = (lane & 7) + ((lane >> 4) & 1) * 8;
    const int bkoff  = ((lane >> 3) & 1) * 8;
    uint32_t aAddr[2], bAddr[2];
#pragma unroll
    for (int mi = 0; mi < 2; mi++)
        aAddr[mi] = asB + ((wm * 32 + mi * 16 + rowoff) * PR + akoff) * 2;
#pragma unroll
    for (int p = 0; p < 2; p++)
        bAddr[p] = wsB + ((wn * 32 + p * 16 + noff) * PR + bkoff) * 2;

    auto issue = [&](int s) {
        const int ko = s * 64;
        const uint32_t st = (uint32_t)(s & 1);
#pragma unroll
        for (int i = 0; i < 4; i++)
            cpa16(asB + st * A_STG + cb + (uint32_t)(32 * i) * (PR * 2),
                  aS + (size_t)(32 * i) * DD + ko);
#pragma unroll
        for (int i = 0; i < 2; i++)
            cpa16(wsB + st * W_STG + cb + (uint32_t)(32 * i) * (PR * 2),
                  wS + (size_t)(32 * i) * DD + ko);
        CP_COMMIT();
    };

    issue(0);

    const int NIT = DD / 64;   // 16
    for (int it = 0; it < NIT; it++) {
        asm volatile("cp.async.wait_group 0;");
        __syncthreads();
        if (it + 1 < NIT) issue(it + 1);

        const uint32_t offA = (uint32_t)(it & 1) * A_STG;
        const uint32_t offB = (uint32_t)(it & 1) * W_STG;
#pragma unroll
        for (int ks = 0; ks < 4; ks++) {
            uint32_t af[2][4];
#pragma unroll
            for (int mi = 0; mi < 2; mi++)
                ldm4(af[mi], aAddr[mi] + offA + ks * 32);
            uint32_t bf[4][2];
#pragma unroll
            for (int p = 0; p < 2; p++) {
                uint32_t tmp[4];
                ldm4(tmp, bAddr[p] + offB + ks * 32);
                bf[2 * p][0] = tmp[0]; bf[2 * p][1] = tmp[1];
                bf[2 * p + 1][0] = tmp[2]; bf[2 * p + 1][1] = tmp[3];
            }
#pragma unroll
            for (int mi = 0; mi < 2; mi++)
#pragma unroll
                for (int ni = 0; ni < 4; ni++)
                    mma16(acc[mi][ni], af[mi], bf[ni]);
        }
    }
}

// ---------------------------------------------------------------------------
// QKV projections (half in/out): Y = X @ W^T + b -> head-split [B,H,S,DK]
// ---------------------------------------------------------------------------
__global__ __launch_bounds__(256, 3) void qkv_proj_kernel(
    const float* __restrict__ bq, const float* __restrict__ bk,
    const float* __restrict__ bv)
{
    extern __shared__ __half smem[];

    const __half* A; const __half* W; const float* bias; __half* out;
    if (blockIdx.z == 0)      { A = g_qh; W = g_wqh; bias = bq; out = g_Q; }
    else if (blockIdx.z == 1) { A = g_kh; W = g_wkh; bias = bk; out = g_K; }
    else                      { A = g_vh; W = g_wvh; bias = bv; out = g_V; }

    float acc[2][4][4];
#pragma unroll
    for (int a = 0; a < 2; a++)
#pragma unroll
        for (int b = 0; b < 4; b++)
#pragma unroll
            for (int c = 0; c < 4; c++) acc[a][b][c] = 0.f;

    gemm_pipe_core(A, W, smem, acc);

    const int lane = threadIdx.x & 31;
    const int warp = threadIdx.x >> 5;
    const int wm = warp >> 1, wn = warp & 1;
    const int qq = lane & 3, l4 = lane >> 2;
    const int m0 = blockIdx.x * 128;
    const int n0 = blockIdx.y * 64;

#pragma unroll
    for (int mi = 0; mi < 2; mi++) {
#pragma unroll
        for (int rr = 0; rr < 2; rr++) {
            int m = m0 + wm * 32 + mi * 16 + l4 + rr * 8;
            int b = m >> 11;
            int s = m & 2047;
#pragma unroll
            for (int ni = 0; ni < 4; ni++) {
                int n  = n0 + wn * 32 + ni * 8 + 2 * qq;
                int h  = n >> 6;
                int dk = n & 63;
                __half2 hv = __floats2half2_rn(acc[mi][ni][rr * 2 + 0] + bias[n],
                                               acc[mi][ni][rr * 2 + 1] + bias[n + 1]);
                *(__half2*)&out[((size_t)(b * HH + h) * SS + s) * DKK + dk] = hv;
            }
        }
    }
}

// ---------------------------------------------------------------------------
// Output projection: out(f32) = g_ATT(half) @ Wo^T + bo
// ---------------------------------------------------------------------------
__global__ __launch_bounds__(256, 3) void out_proj_kernel(
    const float* __restrict__ bo, float* __restrict__ out)
{
    extern __shared__ __half smem[];

    float acc[2][4][4];
#pragma unroll
    for (int a = 0; a < 2; a++)
#pragma unroll
        for (int b = 0; b < 4; b++)
#pragma unroll
            for (int c = 0; c < 4; c++) acc[a][b][c] = 0.f;

    gemm_pipe_core(g_ATT, g_woh, smem, acc);

    const int lane = threadIdx.x & 31;
    const int warp = threadIdx.x >> 5;
    const int wm = warp >> 1, wn = warp & 1;
    const int qq = lane & 3, l4 = lane >> 2;
    const int m0 = blockIdx.x * 128;
    const int n0 = blockIdx.y * 64;

#pragma unroll
    for (int mi = 0; mi < 2; mi++) {
#pragma unroll
        for (int rr = 0; rr < 2; rr++) {
            int m = m0 + wm * 32 + mi * 16 + l4 + rr * 8;
#pragma unroll
            for (int ni = 0; ni < 4; ni++) {
                int n = n0 + wn * 32 + ni * 8 + 2 * qq;
                float2 rv;
                rv.x = acc[mi][ni][rr * 2 + 0] + bo[n];
                rv.y = acc[mi][ni][rr * 2 + 1] + bo[n + 1];
                *(float2*)&out[(size_t)m * DD + n] = rv;
            }
        }
    }
}

// ---------------------------------------------------------------------------
// Flash attention (causal), FP16 mma + ldmatrix + cp.async.
// 4-stage KV ring, tiles processed in PAIRS: one wait+sync per 128 keys.
// Heavy q-tiles launch first (bx reversed) for better tail packing.
// ---------------------------------------------------------------------------
#define AR 72
#define Q_HALVES (128 * AR)
#define KV_HALVES (64 * AR)
#define ATTN_SMEM ((Q_HALVES + 8 * KV_HALVES) * 2)   // 92160 B

__global__ __launch_bounds__(256, 2) void attn_kernel()
{
    extern __shared__ __half sm[];
    __half* Qs = sm;

    const int t    = threadIdx.x;
    const int lane = t & 31;
    const int w    = t >> 5;
    const int qq   = lane & 3;
    const int l4   = lane >> 2;

    const int bx = (int)gridDim.x - 1 - (int)blockIdx.x;   // heavy first
    const int h  = blockIdx.y;
    const int b  = blockIdx.z;

    const __half* Qbase = g_Q + ((size_t)(b * HH + h) * SS) * DKK;
    const __half* Kbase = g_K + ((size_t)(b * HH + h) * SS) * DKK;
    const __half* Vbase = g_V + ((size_t)(b * HH + h) * SS) * DKK;

    uint32_t ksB[4], vsB[4];
#pragma unroll
    for (int i = 0; i < 4; i++) {
        ksB[i] = su(Qs + Q_HALVES + (size_t)i * KV_HALVES);
        vsB[i] = su(Qs + Q_HALVES + (size_t)(4 + i) * KV_HALVES);
    }

    const int qr = t >> 3;
    const int qc = (t & 7) * 16;
    const int kr = t >> 3;
    const int kc = (t & 7) * 16;

    // Issue Q (own commit group)
    {
        uint32_t qdst = su(Qs);
#pragma unroll
        for (int i = 0; i < 4; i++) {
            int r = qr + 32 * i;
            cpa16(qdst + r * (AR * 2) + qc, (const char*)(Qbase + (size_t)(bx * 128 + r) * DKK) + qc);
        }
    }
    CP_COMMIT();

    // Issue a PAIR of KV tiles as one commit group
    auto issue_group = [&](int g) {
#pragma unroll
        for (int tt = 0; tt < 2; tt++) {
            const int kt = 2 * g + tt;
            const __half* Kt = Kbase + (size_t)kt * 64 * DKK;
            const __half* Vt = Vbase + (size_t)kt * 64 * DKK;
            const int st = kt & 3;
#pragma unroll
            for (int i = 0; i < 2; i++) {
                int r = kr + 32 * i;
                cpa16(ksB[st] + r * (AR * 2) + kc, (const char*)(Kt + (size_t)r * DKK) + kc);
                cpa16(vsB[st] + r * (AR * 2) + kc, (const char*)(Vt + (size_t)r * DKK) + kc);
            }
        }
        CP_COMMIT();
    };

    issue_group(0);

    // Wait for Q (group 0 may remain in flight), extract Q fragments
    asm volatile("cp.async.wait_group 1;");
    __syncthreads();

    const int rowoff = (lane & 7) + ((lane >> 3) & 1) * 8;
    const int akoff  = ((lane >> 4) & 1) * 8;
    const int noff   = (lane & 7) + ((lane >> 4) & 1) * 8;
    const int bkoff  = ((lane >> 3) & 1) * 8;
    const int vkoff  = ((lane >> 4) & 1) * 8;

    uint32_t aq[4][4];
#pragma unroll
    for (int g = 0; g < 4; g++)
        ldm4(aq[g], su(&Qs[(16 * w + rowoff) * AR + g * 16 + akoff]));

    const int rl = 16 * w + l4;
    const int row_lo = bx * 128 + rl;
    const int row_hi = row_lo + 8;

    float m_lo = -1e30f, m_hi = -1e30f, l_lo = 0.f, l_hi = 0.f;
    float Oacc[8][4];
#pragma unroll
    for (int j = 0; j < 8; j++)
#pragma unroll
        for (int c = 0; c < 4; c++) Oacc[j][c] = 0.f;

    // Process one 64-key tile (stage kt&3)
    auto process_tile = [&](int kt) {
        const int st = kt & 3;

        float Sacc[8][4];
#pragma unroll
        for (int j = 0; j < 8; j++)
#pragma unroll
            for (int c = 0; c < 4; c++) Sacc[j][c] = 0.f;

#pragma unroll
        for (int g = 0; g < 4; g++) {
#pragma unroll
            for (int p = 0; p < 4; p++) {
                uint32_t tmp[4];
                ldm4(tmp, ksB[st] + ((p * 16 + noff) * AR + g * 16 + bkoff) * 2);
                mma16(Sacc[2 * p],     aq[g], tmp);
                mma16(Sacc[2 * p + 1], aq[g], tmp + 2);
            }
        }

#pragma unroll
        for (int j = 0; j < 8; j++)
#pragma unroll
            for (int c = 0; c < 4; c++) Sacc[j][c] *= 0.125f;

        if (kt >= 2 * bx) {
#pragma unroll
            for (int j = 0; j < 8; j++) {
                int col = kt * 64 + 8 * j + 2 * qq;
                if (col     > row_lo) Sacc[j][0] = -1e30f;
                if (col + 1 > row_lo) Sacc[j][1] = -1e30f;
                if (col     > row_hi) Sacc[j][2] = -1e30f;
                if (col + 1 > row_hi) Sacc[j][3] = -1e30f;
            }
        }

        float mt_lo = -1e30f, mt_hi = -1e30f;
#pragma unroll
        for (int j = 0; j < 8; j++) {
            mt_lo = fmaxf(mt_lo, fmaxf(Sacc[j][0], Sacc[j][1]));
            mt_hi = fmaxf(mt_hi, fmaxf(Sacc[j][2], Sacc[j][3]));
        }
        mt_lo = fmaxf(mt_lo, __shfl_xor_sync(0xffffffffu, mt_lo, 1));
        mt_lo = fmaxf(mt_lo, __shfl_xor_sync(0xffffffffu, mt_lo, 2));
        mt_hi = fmaxf(mt_hi, __shfl_xor_sync(0xffffffffu, mt_hi, 1));
        mt_hi = fmaxf(mt_hi, __shfl_xor_sync(0xffffffffu, mt_hi, 2));

        float mn_lo = fmaxf(m_lo, mt_lo);
        float mn_hi = fmaxf(m_hi, mt_hi);
        float al_lo = __expf(m_lo - mn_lo);
        float al_hi = __expf(m_hi - mn_hi);

        float ls_lo = 0.f, ls_hi = 0.f;
#pragma unroll
        for (int j = 0; j < 8; j++) {
            Sacc[j][0] = __expf(Sacc[j][0] - mn_lo);
            Sacc[j][1] = __expf(Sacc[j][1] - mn_lo);
            Sacc[j][2] = __expf(Sacc[j][2] - mn_hi);
            Sacc[j][3] = __expf(Sacc[j][3] - mn_hi);
            ls_lo += Sacc[j][0] + Sacc[j][1];
            ls_hi += Sacc[j][2] + Sacc[j][3];
        }
        ls_lo += __shfl_xor_sync(0xffffffffu, ls_lo, 1);
        ls_lo += __shfl_xor_sync(0xffffffffu, ls_lo, 2);
        ls_hi += __shfl_xor_sync(0xffffffffu, ls_hi, 1);
        ls_hi += __shfl_xor_sync(0xffffffffu, ls_hi, 2);

        l_lo = l_lo * al_lo + ls_lo;
        l_hi = l_hi * al_hi + ls_hi;
        m_lo = mn_lo;
        m_hi = mn_hi;

        uint32_t ap[4][4];
#pragma unroll
        for (int g = 0; g < 4; g++) {
            ap[g][0] = packh2(Sacc[2 * g][0],     Sacc[2 * g][1]);
            ap[g][1] = packh2(Sacc[2 * g][2],     Sacc[2 * g][3]);
            ap[g][2] = packh2(Sacc[2 * g + 1][0], Sacc[2 * g + 1][1]);
            ap[g][3] = packh2(Sacc[2 * g + 1][2], Sacc[2 * g + 1][3]);
        }

#pragma unroll
        for (int j = 0; j < 8; j++) {
            Oacc[j][0] *= al_lo;
            Oacc[j][1] *= al_lo;
            Oacc[j][2] *= al_hi;
            Oacc[j][3] *= al_hi;
        }

#pragma unroll
        for (int g = 0; g < 4; g++) {
#pragma unroll
            for (int p = 0; p < 4; p++) {
                uint32_t tmp[4];
                ldm4t(tmp, vsB[st] + ((g * 16 + rowoff) * AR + p * 16 + vkoff) * 2);
                mma16(Oacc[2 * p],     ap[g], tmp);
                mma16(Oacc[2 * p + 1], ap[g], tmp + 2);
            }
        }
    };

    // Main loop: bx+1 iterations, each consumes a pair of tiles.
    // Iter j: wait group j (all outstanding), sync (all warps done with group
    // j-1, whose stages group j+1 reuses), prefetch group j+1, compute pair.
    for (int j = 0; j <= bx; j++) {
        asm volatile("cp.async.wait_group 0;");
        __syncthreads();
        if (j < bx) issue_group(j + 1);
        process_tile(2 * j);
        process_tile(2 * j + 1);
    }

    float il_lo = 1.f / l_lo;
    float il_hi = 1.f / l_hi;
    __half* out_lo = g_ATT + ((size_t)(b * SS + row_lo)) * DD + h * DKK;
    __half* out_hi = g_ATT + ((size_t)(b * SS + row_hi)) * DD + h * DKK;
#pragma unroll
    for (int j = 0; j < 8; j++) {
        int dk = 8 * j + 2 * qq;
        *(__half2*)&out_lo[dk] = __floats2half2_rn(Oacc[j][0] * il_lo, Oacc[j][1] * il_lo);
        *(__half2*)&out_hi[dk] = __floats2half2_rn(Oacc[j][2] * il_hi, Oacc[j][3] * il_hi);
    }
}

// ---------------------------------------------------------------------------
// Entry point. Inputs: q,k,v,mask,w_q,b_q,w_k,b_k,w_v,b_v,w_o,b_o
// ---------------------------------------------------------------------------
extern "C" void kernel_launch(void* const* d_in, const int* in_sizes, int n_in,
                              void* d_out, int out_size)
{
    const float* q  = (const float*)d_in[0];
    const float* k  = (const float*)d_in[1];
    const float* v  = (const float*)d_in[2];
    const float* wq = (const float*)d_in[4];
    const float* bq = (const float*)d_in[5];
    const float* wk = (const float*)d_in[6];
    const float* bk = (const float*)d_in[7];
    const float* wv = (const float*)d_in[8];
    const float* bv = (const float*)d_in[9];
    const float* wo = (const float*)d_in[10];
    const float* bo = (const float*)d_in[11];
    float* out = (float*)d_out;

    f2h_all_kernel<<<(NCONV_TOT + 255) / 256, 256>>>(
        (const float4*)q, (const float4*)k, (const float4*)v,
        (const float4*)wq, (const float4*)wk, (const float4*)wv, (const float4*)wo);

    cudaFuncSetAttribute(qkv_proj_kernel, cudaFuncAttributeMaxDynamicSharedMemorySize, GEMM_SMEM);
    dim3 gproj(MTOT / 128, DD / 64, 3);
    qkv_proj_kernel<<<gproj, 256, GEMM_SMEM>>>(bq, bk, bv);

    cudaFuncSetAttribute(attn_kernel, cudaFuncAttributeMaxDynamicSharedMemorySize, ATTN_SMEM);
    dim3 gattn(SS / 128, HH, BB);
    attn_kernel<<<gattn, 256, ATTN_SMEM>>>();

    cudaFuncSetAttribute(out_proj_kernel, cudaFuncAttributeMaxDynamicSharedMemorySize, GEMM_SMEM);
    dim3 gout(MTOT / 128, DD / 64, 1);
    out_proj_kernel<<<gout, 256, GEMM_SMEM>>>(bo, out);
}